// round 1
// baseline (speedup 1.0000x reference)
#include <cuda_runtime.h>
#include <cstdint>

// Problem constants
#define BB   4
#define SS   2048
#define DD   1024
#define HH   16
#define DKK  64

#define GM   (BB*SS)      // 8192 rows for projection GEMMs
#define GK   DD           // 1024
#define GN   DD           // 1024

// ---------------------------------------------------------------------------
// Scratch (device globals: allocation-free per harness rules)
// ---------------------------------------------------------------------------
__device__ float gQ[BB*SS*DD];
__device__ float gK[BB*SS*DD];
__device__ float gV[BB*SS*DD];
__device__ float gC[BB*SS*DD];

// ---------------------------------------------------------------------------
// Helpers
// ---------------------------------------------------------------------------
__device__ __forceinline__ unsigned f2tf(float f) {
    unsigned r;
    asm("cvt.rna.tf32.f32 %0, %1;" : "=r"(r) : "f"(f));
    return r;
}
__device__ __forceinline__ float ex2(float x) {
    float r;
    asm("ex2.approx.ftz.f32 %0, %1;" : "=f"(r) : "f"(x));
    return r;
}
// D += A*B, m16n8k8 tf32
__device__ __forceinline__ void mma_tf32(float& d0, float& d1, float& d2, float& d3,
                                         unsigned a0, unsigned a1, unsigned a2, unsigned a3,
                                         unsigned b0, unsigned b1) {
    asm("mma.sync.aligned.m16n8k8.row.col.f32.tf32.tf32.f32 "
        "{%0,%1,%2,%3},{%4,%5,%6,%7},{%8,%9},{%0,%1,%2,%3};"
        : "+f"(d0), "+f"(d1), "+f"(d2), "+f"(d3)
        : "r"(a0), "r"(a1), "r"(a2), "r"(a3), "r"(b0), "r"(b1));
}

// ---------------------------------------------------------------------------
// GEMM: C[M,N] = X[M,K] @ W[K,N] + bias[N]   (M=8192, K=N=1024, exact tiles)
// Block tile 128x128x32, 256 threads (8 warps, warp tile 64x32)
// ---------------------------------------------------------------------------
#define ASTR 36
#define BSTR 132

__global__ __launch_bounds__(256)
void gemm_bias(const float* __restrict__ X, const float* __restrict__ W,
               const float* __restrict__ bias, float* __restrict__ C) {
    __shared__ unsigned As[128 * ASTR];
    __shared__ unsigned Bs[32 * BSTR];

    const int tid  = threadIdx.x;
    const int wid  = tid >> 5;
    const int lane = tid & 31;
    const int g    = lane >> 2;   // groupID
    const int t    = lane & 3;    // threadID_in_group
    const int wm   = wid & 1;     // 0..1 (m)
    const int wn   = wid >> 1;    // 0..3 (n)
    const int m0   = blockIdx.y * 128;
    const int n0   = blockIdx.x * 128;

    float acc[4][4][4];
#pragma unroll
    for (int mf = 0; mf < 4; mf++)
#pragma unroll
        for (int nf = 0; nf < 4; nf++)
#pragma unroll
            for (int r = 0; r < 4; r++) acc[mf][nf][r] = 0.f;

    for (int kt = 0; kt < GK / 32; kt++) {
        __syncthreads();
        // A tile: 128x32 (1024 float4)
#pragma unroll
        for (int i = 0; i < 4; i++) {
            int idx = tid + i * 256;
            int r = idx >> 3, c4 = idx & 7;
            float4 v = *(const float4*)(X + (size_t)(m0 + r) * GK + kt * 32 + c4 * 4);
            unsigned* dst = &As[r * ASTR + c4 * 4];
            dst[0] = f2tf(v.x); dst[1] = f2tf(v.y); dst[2] = f2tf(v.z); dst[3] = f2tf(v.w);
        }
        // B tile: 32x128 (1024 float4)
#pragma unroll
        for (int i = 0; i < 4; i++) {
            int idx = tid + i * 256;
            int r = idx >> 5, c4 = idx & 31;
            float4 v = *(const float4*)(W + (size_t)(kt * 32 + r) * GN + n0 + c4 * 4);
            unsigned* dst = &Bs[r * BSTR + c4 * 4];
            dst[0] = f2tf(v.x); dst[1] = f2tf(v.y); dst[2] = f2tf(v.z); dst[3] = f2tf(v.w);
        }
        __syncthreads();

#pragma unroll
        for (int ks = 0; ks < 4; ks++) {
            unsigned a[4][4];
#pragma unroll
            for (int mf = 0; mf < 4; mf++) {
                int rb = wm * 64 + mf * 16;
                a[mf][0] = As[(rb + g)     * ASTR + ks * 8 + t];
                a[mf][1] = As[(rb + g + 8) * ASTR + ks * 8 + t];
                a[mf][2] = As[(rb + g)     * ASTR + ks * 8 + t + 4];
                a[mf][3] = As[(rb + g + 8) * ASTR + ks * 8 + t + 4];
            }
#pragma unroll
            for (int nf = 0; nf < 4; nf++) {
                unsigned b0 = Bs[(ks * 8 + t)     * BSTR + wn * 32 + nf * 8 + g];
                unsigned b1 = Bs[(ks * 8 + t + 4) * BSTR + wn * 32 + nf * 8 + g];
#pragma unroll
                for (int mf = 0; mf < 4; mf++)
                    mma_tf32(acc[mf][nf][0], acc[mf][nf][1], acc[mf][nf][2], acc[mf][nf][3],
                             a[mf][0], a[mf][1], a[mf][2], a[mf][3], b0, b1);
            }
        }
    }

    // Epilogue
#pragma unroll
    for (int mf = 0; mf < 4; mf++) {
#pragma unroll
        for (int nf = 0; nf < 4; nf++) {
            int row = m0 + wm * 64 + mf * 16 + g;
            int col = n0 + wn * 32 + nf * 8 + 2 * t;
            float bv0 = bias[col], bv1 = bias[col + 1];
            C[(size_t)row * GN + col]           = acc[mf][nf][0] + bv0;
            C[(size_t)row * GN + col + 1]       = acc[mf][nf][1] + bv1;
            C[(size_t)(row + 8) * GN + col]     = acc[mf][nf][2] + bv0;
            C[(size_t)(row + 8) * GN + col + 1] = acc[mf][nf][3] + bv1;
        }
    }
}

// ---------------------------------------------------------------------------
// Flash attention: grid (S/128, H, B). 256 threads; warp w owns q rows
// [w*16, w*16+16) x all 128 kv columns of each tile -> shuffle-only softmax.
// Q fragments register-resident (scale folded in). K,V,P staged in smem (tf32).
// ---------------------------------------------------------------------------
#define KSTR 68
#define PSTR 132
#define ATTN_SMEM ((128*KSTR*2 + 128*PSTR) * 4)   // 137216 bytes

__global__ __launch_bounds__(256)
void attn_kernel(const float* __restrict__ gq, const float* __restrict__ gk,
                 const float* __restrict__ gv, float* __restrict__ gc) {
    extern __shared__ unsigned smem[];
    unsigned* Ks = smem;
    unsigned* Vs = smem + 128 * KSTR;
    unsigned* Ps = smem + 2 * 128 * KSTR;

    const int b  = blockIdx.z;
    const int h  = blockIdx.y;
    const int q0 = blockIdx.x * 128;
    const int tid  = threadIdx.x;
    const int wid  = tid >> 5;
    const int lane = tid & 31;
    const int g    = lane >> 2;
    const int t    = lane & 3;
    const float scale = 0.125f;                 // 1/sqrt(64)
    const float L2E   = 1.44269504f;

    // Q fragments: 16 rows x 64 k, 8 k-steps
    unsigned qf[8][4];
    {
        const float* Qb = gq + ((size_t)(b * SS + q0 + wid * 16)) * DD + h * DKK;
#pragma unroll
        for (int ks = 0; ks < 8; ks++) {
            qf[ks][0] = f2tf(Qb[(size_t)g * DD + ks * 8 + t] * scale);
            qf[ks][1] = f2tf(Qb[(size_t)(g + 8) * DD + ks * 8 + t] * scale);
            qf[ks][2] = f2tf(Qb[(size_t)g * DD + ks * 8 + t + 4] * scale);
            qf[ks][3] = f2tf(Qb[(size_t)(g + 8) * DD + ks * 8 + t + 4] * scale);
        }
    }

    float mr0 = -1e30f, mr1 = -1e30f, l0 = 0.f, l1 = 0.f;
    float oacc[8][4];
#pragma unroll
    for (int nf = 0; nf < 8; nf++)
#pragma unroll
        for (int r = 0; r < 4; r++) oacc[nf][r] = 0.f;

    const float* Kb = gk + ((size_t)b * SS) * DD + h * DKK;
    const float* Vb = gv + ((size_t)b * SS) * DD + h * DKK;

    for (int kt = 0; kt < SS / 128; kt++) {
        __syncthreads();
        // load K,V tiles: 128 x 64 each (2048 float4 each), convert to tf32
#pragma unroll
        for (int i = 0; i < 8; i++) {
            int idx = tid + i * 256;
            int r = idx >> 4, c4 = idx & 15;
            float4 kv = *(const float4*)(Kb + (size_t)(kt * 128 + r) * DD + c4 * 4);
            unsigned* dk = &Ks[r * KSTR + c4 * 4];
            dk[0] = f2tf(kv.x); dk[1] = f2tf(kv.y); dk[2] = f2tf(kv.z); dk[3] = f2tf(kv.w);
            float4 vv = *(const float4*)(Vb + (size_t)(kt * 128 + r) * DD + c4 * 4);
            unsigned* dv = &Vs[r * KSTR + c4 * 4];
            dv[0] = f2tf(vv.x); dv[1] = f2tf(vv.y); dv[2] = f2tf(vv.z); dv[3] = f2tf(vv.w);
        }
        __syncthreads();

        // S = Q K^T (pre-scaled): 16 x 128 per warp
        float sacc[16][4];
#pragma unroll
        for (int nf = 0; nf < 16; nf++)
#pragma unroll
            for (int r = 0; r < 4; r++) sacc[nf][r] = 0.f;

#pragma unroll
        for (int ks = 0; ks < 8; ks++) {
#pragma unroll
            for (int nf = 0; nf < 16; nf++) {
                unsigned b0 = Ks[(nf * 8 + g) * KSTR + ks * 8 + t];
                unsigned b1 = Ks[(nf * 8 + g) * KSTR + ks * 8 + t + 4];
                mma_tf32(sacc[nf][0], sacc[nf][1], sacc[nf][2], sacc[nf][3],
                         qf[ks][0], qf[ks][1], qf[ks][2], qf[ks][3], b0, b1);
            }
        }

        // online softmax (rows g and g+8; reduce across quad lanes t)
        float rmax0 = -1e30f, rmax1 = -1e30f;
#pragma unroll
        for (int nf = 0; nf < 16; nf++) {
            rmax0 = fmaxf(rmax0, fmaxf(sacc[nf][0], sacc[nf][1]));
            rmax1 = fmaxf(rmax1, fmaxf(sacc[nf][2], sacc[nf][3]));
        }
        rmax0 = fmaxf(rmax0, __shfl_xor_sync(0xffffffffu, rmax0, 1));
        rmax0 = fmaxf(rmax0, __shfl_xor_sync(0xffffffffu, rmax0, 2));
        rmax1 = fmaxf(rmax1, __shfl_xor_sync(0xffffffffu, rmax1, 1));
        rmax1 = fmaxf(rmax1, __shfl_xor_sync(0xffffffffu, rmax1, 2));
        float mn0 = fmaxf(mr0, rmax0), mn1 = fmaxf(mr1, rmax1);
        float alpha0 = ex2((mr0 - mn0) * L2E);
        float alpha1 = ex2((mr1 - mn1) * L2E);
        mr0 = mn0; mr1 = mn1;

        float rs0 = 0.f, rs1 = 0.f;
        const int pr0 = wid * 16 + g;
#pragma unroll
        for (int nf = 0; nf < 16; nf++) {
            float p0 = ex2((sacc[nf][0] - mn0) * L2E);
            float p1 = ex2((sacc[nf][1] - mn0) * L2E);
            float p2 = ex2((sacc[nf][2] - mn1) * L2E);
            float p3 = ex2((sacc[nf][3] - mn1) * L2E);
            rs0 += p0 + p1;
            rs1 += p2 + p3;
            int c = nf * 8 + 2 * t;
            Ps[pr0 * PSTR + c]           = f2tf(p0);
            Ps[pr0 * PSTR + c + 1]       = f2tf(p1);
            Ps[(pr0 + 8) * PSTR + c]     = f2tf(p2);
            Ps[(pr0 + 8) * PSTR + c + 1] = f2tf(p3);
        }
        rs0 += __shfl_xor_sync(0xffffffffu, rs0, 1);
        rs0 += __shfl_xor_sync(0xffffffffu, rs0, 2);
        rs1 += __shfl_xor_sync(0xffffffffu, rs1, 1);
        rs1 += __shfl_xor_sync(0xffffffffu, rs1, 2);
        l0 = l0 * alpha0 + rs0;
        l1 = l1 * alpha1 + rs1;
#pragma unroll
        for (int nf = 0; nf < 8; nf++) {
            oacc[nf][0] *= alpha0; oacc[nf][1] *= alpha0;
            oacc[nf][2] *= alpha1; oacc[nf][3] *= alpha1;
        }
        __syncwarp();

        // O += P V : M=16, N=64, K=128 per warp
#pragma unroll
        for (int ks = 0; ks < 16; ks++) {
            unsigned a0 = Ps[(wid * 16 + g)     * PSTR + ks * 8 + t];
            unsigned a1 = Ps[(wid * 16 + g + 8) * PSTR + ks * 8 + t];
            unsigned a2 = Ps[(wid * 16 + g)     * PSTR + ks * 8 + t + 4];
            unsigned a3 = Ps[(wid * 16 + g + 8) * PSTR + ks * 8 + t + 4];
#pragma unroll
            for (int nf = 0; nf < 8; nf++) {
                unsigned b0 = Vs[(ks * 8 + t)     * KSTR + nf * 8 + g];
                unsigned b1 = Vs[(ks * 8 + t + 4) * KSTR + nf * 8 + g];
                mma_tf32(oacc[nf][0], oacc[nf][1], oacc[nf][2], oacc[nf][3],
                         a0, a1, a2, a3, b0, b1);
            }
        }
    }

    // epilogue: normalize, write ctx in [B,S,D] layout
    float inv0 = 1.f / l0, inv1 = 1.f / l1;
    float* Cb = gc + ((size_t)(b * SS + q0 + wid * 16)) * DD + h * DKK;
#pragma unroll
    for (int nf = 0; nf < 8; nf++) {
        int c = nf * 8 + 2 * t;
        Cb[(size_t)g * DD + c]           = oacc[nf][0] * inv0;
        Cb[(size_t)g * DD + c + 1]       = oacc[nf][1] * inv0;
        Cb[(size_t)(g + 8) * DD + c]     = oacc[nf][2] * inv1;
        Cb[(size_t)(g + 8) * DD + c + 1] = oacc[nf][3] * inv1;
    }
}

// ---------------------------------------------------------------------------
// Launch
// ---------------------------------------------------------------------------
extern "C" void kernel_launch(void* const* d_in, const int* in_sizes, int n_in,
                              void* d_out, int out_size) {
    const float* query = (const float*)d_in[0];
    const float* key_  = (const float*)d_in[1];
    const float* value = (const float*)d_in[2];
    const float* Wq = (const float*)d_in[3];
    const float* bq = (const float*)d_in[4];
    const float* Wk = (const float*)d_in[5];
    const float* bk = (const float*)d_in[6];
    const float* Wv = (const float*)d_in[7];
    const float* bv = (const float*)d_in[8];
    const float* Wo = (const float*)d_in[9];
    const float* bo = (const float*)d_in[10];
    float* out = (float*)d_out;

    float *pQ, *pK, *pV, *pC;
    cudaGetSymbolAddress((void**)&pQ, gQ);
    cudaGetSymbolAddress((void**)&pK, gK);
    cudaGetSymbolAddress((void**)&pV, gV);
    cudaGetSymbolAddress((void**)&pC, gC);

    cudaFuncSetAttribute(attn_kernel, cudaFuncAttributeMaxDynamicSharedMemorySize, ATTN_SMEM);

    dim3 ggrid(GN / 128, GM / 128);   // (8, 64)
    gemm_bias<<<ggrid, 256>>>(query, Wq, bq, pQ);
    gemm_bias<<<ggrid, 256>>>(key_,  Wk, bk, pK);
    gemm_bias<<<ggrid, 256>>>(value, Wv, bv, pV);

    attn_kernel<<<dim3(SS / 128, HH, BB), 256, ATTN_SMEM>>>(pQ, pK, pV, pC);

    gemm_bias<<<ggrid, 256>>>(pC, Wo, bo, out);
}